// round 13
// baseline (speedup 1.0000x reference)
#include <cuda_runtime.h>
#include <cuda_fp16.h>
#include <math.h>
#include <stdint.h>

// ---------------- Problem constants ----------------
#define T_TOKENS 16384
#define D_MODEL  4096
#define N_EXP    128

// ---------------- GEMM config ----------------
#define BM   128
#define BN   128
#define CK   64                 // K per chunk (64 fp16 = 128B row)
#define NTILE (T_TOKENS / BM)   // 128 token tiles
#define CPT   (D_MODEL / CK)    // 64 chunks per tile
#define NUNITS (NTILE * CPT)    // 8192 chunk-units
#define TPB  640                // 16 consumer warps (4x4) + 4 producer warps

// smem: two 64KB stages; each: Ah Al Bh Bl (16KB each, 128 rows x 128B)
#define STAGE_BYTES 65536
#define OFF_AH 0
#define OFF_AL 16384
#define OFF_BH 32768
#define OFF_BL 49152
#define SMEM_TOTAL (2 * STAGE_BYTES)   // 131072

#define SWZ(b) ((b) ^ (((b) >> 3) & 0x70))

// Named barriers (count = all 640 threads): FULL[s]=1+s, EMPTY[s]=3+s
#define BAR_SYNC(id)   asm volatile("bar.sync %0, %1;"   :: "r"(id), "r"(TPB) : "memory")
#define BAR_ARRIVE(id) asm volatile("bar.arrive %0, %1;" :: "r"(id), "r"(TPB) : "memory")

// ---------------- sm_80-level PTX helpers ----------------
__device__ __forceinline__ uint32_t smem_to_u32(const void* p) {
    uint32_t a;
    asm("{ .reg .u64 t; cvta.to.shared.u64 t, %1; cvt.u32.u64 %0, t; }"
        : "=r"(a) : "l"(p));
    return a;
}
#define LDSM4(r0, r1, r2, r3, addr) \
    asm volatile("ldmatrix.sync.aligned.m8n8.x4.shared.b16 {%0,%1,%2,%3}, [%4];" \
        : "=r"(r0), "=r"(r1), "=r"(r2), "=r"(r3) : "r"(addr))
#define MMA16816(c, a, b0, b1) \
    asm volatile("mma.sync.aligned.m16n8k16.row.col.f32.f16.f16.f32 " \
        "{%0,%1,%2,%3},{%4,%5,%6,%7},{%8,%9},{%0,%1,%2,%3};" \
        : "+f"((c)[0]), "+f"((c)[1]), "+f"((c)[2]), "+f"((c)[3]) \
        : "r"((a)[0]), "r"((a)[1]), "r"((a)[2]), "r"((a)[3]), "r"(b0), "r"(b1))
#define MMA16816_H(c, a, b0, b1) \
    asm volatile("mma.sync.aligned.m16n8k16.row.col.f16.f16.f16.f16 " \
        "{%0,%1},{%2,%3,%4,%5},{%6,%7},{%0,%1};" \
        : "+r"((c)[0]), "+r"((c)[1]) \
        : "r"((a)[0]), "r"((a)[1]), "r"((a)[2]), "r"((a)[3]), "r"(b0), "r"(b1))
__device__ __forceinline__ void cp16(uint32_t dst, const void* src) {
    asm volatile("cp.async.cg.shared.global [%0], [%1], 16;"
                 :: "r"(dst), "l"(src));
}
#define CP_COMMIT() asm volatile("cp.async.commit_group;" ::: "memory")
#define CP_WAIT0()  asm volatile("cp.async.wait_group 0;" ::: "memory")

// ---------------- Global scratch ----------------
__device__ float g_me[N_EXP];
__device__ int   g_ce[N_EXP];
__device__ __half g_Bh[N_EXP * D_MODEL];
__device__ __half g_Bl[N_EXP * D_MODEL];
__device__ float g_logits[NTILE * BM * BN];   // 8 MB partial-logit buffer

// fp16 2-way split, UNSCALED residual: f = h + l (l may be subnormal)
__device__ __forceinline__ void split2(float f, __half& h, __half& l) {
    h = __float2half_rn(f);
    l = __float2half_rn(f - __half2float(h));
}
__device__ __forceinline__ uint32_t pack2h(__half a, __half b) {
    return (uint32_t)__half_as_ushort(a) |
           ((uint32_t)__half_as_ushort(b) << 16);
}

// prep: split wg, zero me/ce, zero g_logits. grid 2048 x 256 = 524288 threads.
__global__ void prep_b_kernel(const float* __restrict__ wg) {
    int idx = blockIdx.x * blockDim.x + threadIdx.x;  // 0..524287
    if (idx < N_EXP) { g_me[idx] = 0.0f; g_ce[idx] = 0; }
    ((float4*)g_logits)[idx] = make_float4(0.f, 0.f, 0.f, 0.f);
    if (idx < (N_EXP * D_MODEL / 4)) {
        float4 v = ((const float4*)wg)[idx];
        float f[4] = {v.x, v.y, v.z, v.w};
        __half h[4], l[4];
#pragma unroll
        for (int q = 0; q < 4; q++) split2(f[q], h[q], l[q]);
        ((uint2*)g_Bh)[idx] = make_uint2(pack2h(h[0], h[1]), pack2h(h[2], h[3]));
        ((uint2*)g_Bl)[idx] = make_uint2(pack2h(l[0], l[1]), pack2h(l[2], l[3]));
    }
}

// top-2: (v1,i1) >= (v2,i2); ties -> smaller index (jax top_k semantics)
__device__ __forceinline__ void top2_upd(float& v1, int& i1, float& v2, int& i2,
                                         float v, int i) {
    if (v > v1 || (v == v1 && i < i1)) {
        v2 = v1; i2 = i1; v1 = v; i1 = i;
    } else if (v > v2 || (v == v2 && i < i2)) {
        v2 = v; i2 = i;
    }
}

// Flush accumulators into the tile's gmem logits (atomicAdd), then zero them.
__device__ __forceinline__ void flush_accs(int tile, int mw, int nw, int gid, int tig,
                                           float acc[2][4][4], uint32_t accr[2][4][2]) {
    float* dst = g_logits + (size_t)tile * (BM * BN);
#pragma unroll
    for (int tm = 0; tm < 2; tm++)
#pragma unroll
        for (int tn = 0; tn < 4; tn++) {
            float2 rlo = __half22float2(*(__half2*)&accr[tm][tn][0]);
            float2 rhi = __half22float2(*(__half2*)&accr[tm][tn][1]);
            int r_ = mw * 32 + tm * 16 + gid;
            int c_ = nw * 32 + tn * 8 + tig * 2;
            atomicAdd(&dst[r_ * BN + c_],           acc[tm][tn][0] + rlo.x);
            atomicAdd(&dst[r_ * BN + c_ + 1],       acc[tm][tn][1] + rlo.y);
            atomicAdd(&dst[(r_ + 8) * BN + c_],     acc[tm][tn][2] + rhi.x);
            atomicAdd(&dst[(r_ + 8) * BN + c_ + 1], acc[tm][tn][3] + rhi.y);
#pragma unroll
            for (int q = 0; q < 4; q++) acc[tm][tn][q] = 0.0f;
            accr[tm][tn][0] = 0u; accr[tm][tn][1] = 0u;
        }
}

__global__ void __launch_bounds__(TPB, 1)
gate_kernel(const float* __restrict__ A) {
    extern __shared__ char smem[];
    const uint32_t smem_u = smem_to_u32(smem);
    const int tid  = threadIdx.x;
    const int wid  = tid >> 5;
    const int lane = tid & 31;

    // Persistent work split: chunk-units [u0, u1) for this CTA
    const int G  = gridDim.x;
    const int u0 = (NUNITS * blockIdx.x) / G;
    const int u1 = (NUNITS * (blockIdx.x + 1)) / G;
    const int nu = u1 - u0;

    if (wid < 16) {
        // ================= CONSUMERS: 4(M) x 4(N) warp grid =================
        const int mw = wid >> 2;
        const int nw = wid & 3;
        const int a_mrow = (lane & 7) + ((lane >> 3) & 1) * 8;
        const int a_cofs = ((lane >> 4) & 1) * 16;
        const int b_nrow = (lane & 7) + ((lane >> 4) & 1) * 8;
        const int b_cofs = ((lane >> 3) & 1) * 16;
        const int gid = lane >> 2, tig = lane & 3;

        float    acc[2][4][4];
        uint32_t accr[2][4][2];
#pragma unroll
        for (int i = 0; i < 2; i++)
#pragma unroll
            for (int j = 0; j < 4; j++) {
#pragma unroll
                for (int q = 0; q < 4; q++) acc[i][j][q] = 0.0f;
                accr[i][j][0] = 0u; accr[i][j][1] = 0u;
            }

        int cur_tile = u0 >> 6;
        for (int i = 0; i < nu; i++) {
            const int u = u0 + i;
            const int tile = u >> 6;
            if (tile != cur_tile) {
                flush_accs(cur_tile, mw, nw, gid, tig, acc, accr);
                cur_tile = tile;
            }
            const int s = i & 1;
            const uint32_t cur = smem_u + s * STAGE_BYTES;
            BAR_SYNC(1 + s);

#pragma unroll 1
            for (int ks = 0; ks < 4; ks++) {
                const int kb = ks * 32;
                uint32_t bfh[8], bfl[8];
#pragma unroll
                for (int q = 0; q < 2; q++) {
                    uint32_t bsw = SWZ((uint32_t)((nw * 32 + q * 16 + b_nrow) * 128 + kb + b_cofs));
                    LDSM4(bfh[q*4+0], bfh[q*4+1], bfh[q*4+2], bfh[q*4+3], cur + OFF_BH + bsw);
                    LDSM4(bfl[q*4+0], bfl[q*4+1], bfl[q*4+2], bfl[q*4+3], cur + OFF_BL + bsw);
                }
                uint32_t af[8];
#pragma unroll
                for (int tm = 0; tm < 2; tm++) {
                    uint32_t asw = SWZ((uint32_t)((mw * 32 + tm * 16 + a_mrow) * 128 + kb + a_cofs));
                    LDSM4(af[tm*4+0], af[tm*4+1], af[tm*4+2], af[tm*4+3], cur + OFF_AH + asw);
                }
#pragma unroll
                for (int tm = 0; tm < 2; tm++)
#pragma unroll
                    for (int tn = 0; tn < 4; tn++) {
                        int bq = (tn >> 1) * 4 + (tn & 1) * 2;
                        MMA16816(acc[tm][tn], &af[tm*4], bfh[bq], bfh[bq+1]);
                        MMA16816_H(accr[tm][tn], &af[tm*4], bfl[bq], bfl[bq+1]);
                    }
#pragma unroll
                for (int tm = 0; tm < 2; tm++) {
                    uint32_t asw = SWZ((uint32_t)((mw * 32 + tm * 16 + a_mrow) * 128 + kb + a_cofs));
                    LDSM4(af[tm*4+0], af[tm*4+1], af[tm*4+2], af[tm*4+3], cur + OFF_AL + asw);
                }
#pragma unroll
                for (int tm = 0; tm < 2; tm++)
#pragma unroll
                    for (int tn = 0; tn < 4; tn++) {
                        int bq = (tn >> 1) * 4 + (tn & 1) * 2;
                        MMA16816_H(accr[tm][tn], &af[tm*4], bfh[bq], bfh[bq+1]);
                    }
            }
            BAR_ARRIVE(3 + s);
        }
        flush_accs(cur_tile, mw, nw, gid, tig, acc, accr);
    } else {
        // ================= PRODUCERS: 4 warps, 128 threads =================
        const int ptid = tid - 512;   // 0..127
        for (int i = 0; i < nu; i++) {
            const int u = u0 + i;
            const int row0 = (u >> 6) * BM;
            const int k0   = (u & 63) * CK;
            const int s = i & 1;
            char* stg = smem + s * STAGE_BYTES;
            const uint32_t stg_u = smem_u + s * STAGE_BYTES;

            if (i >= 2) BAR_SYNC(3 + s);

            // B tiles via cp.async (in flight during A work)
#pragma unroll
            for (int j = 0; j < 8; j++) {
                int idx = ptid + j * 128;          // 0..1023
                int r   = idx >> 3;
                int c16 = (idx & 7) * 16;
                size_t g = (size_t)r * D_MODEL + k0 + (c16 >> 1);
                uint32_t sw = SWZ((uint32_t)(r * 128 + c16));
                cp16(stg_u + OFF_BH + sw, g_Bh + g);
                cp16(stg_u + OFF_BL + sw, g_Bl + g);
            }
            CP_COMMIT();

            // A: LDG -> split2 -> STS, 2 batches of 8 float4
#pragma unroll
            for (int bat = 0; bat < 2; bat++) {
                float4 aval[8];
#pragma unroll
                for (int j = 0; j < 8; j++) {
                    int idx = ptid + (bat * 8 + j) * 128;   // 0..2047
                    int r   = idx >> 4;
                    int col = (idx & 15) << 2;
                    aval[j] = *(const float4*)(A + (size_t)(row0 + r) * D_MODEL + k0 + col);
                }
#pragma unroll
                for (int j = 0; j < 8; j++) {
                    int idx = ptid + (bat * 8 + j) * 128;
                    int r   = idx >> 4;
                    int col = (idx & 15) << 2;
                    float f[4] = {aval[j].x, aval[j].y, aval[j].z, aval[j].w};
                    __half h[4], l[4];
#pragma unroll
                    for (int q = 0; q < 4; q++) split2(f[q], h[q], l[q]);
                    uint32_t sw = SWZ((uint32_t)(r * 128 + col * 2));
                    *(uint2*)(stg + OFF_AH + sw) = make_uint2(pack2h(h[0], h[1]), pack2h(h[2], h[3]));
                    *(uint2*)(stg + OFF_AL + sw) = make_uint2(pack2h(l[0], l[1]), pack2h(l[2], l[3]));
                }
            }
            CP_WAIT0();
            BAR_ARRIVE(1 + s);
        }
    }
}

// Epilogue: one CTA per token tile; logits read from gmem.
__global__ void __launch_bounds__(256, 1)
epilogue_kernel(float* __restrict__ out) {
    __shared__ float sMe[N_EXP];
    const int tid  = threadIdx.x;
    const int wid  = tid >> 5;
    const int lane = tid & 31;
    if (tid < N_EXP) sMe[tid] = 0.0f;
    __syncthreads();

    const int tile = blockIdx.x;
    const float* Lg = g_logits + (size_t)tile * (BM * BN);
    const float inv_temp = 1.0f / 0.3f;

    for (int t = wid; t < BM; t += 8) {
        float v[4]; int ix[4];
#pragma unroll
        for (int q = 0; q < 4; q++) {
            ix[q] = lane + q * 32;
            v[q]  = Lg[t * BN + ix[q]];
        }
        float v1 = -INFINITY, v2 = -INFINITY;
        int   i1 = N_EXP, i2 = N_EXP;
#pragma unroll
        for (int q = 0; q < 4; q++) top2_upd(v1, i1, v2, i2, v[q], ix[q]);
#pragma unroll
        for (int off = 16; off > 0; off >>= 1) {
            float ov1 = __shfl_xor_sync(0xffffffffu, v1, off);
            int   oi1 = __shfl_xor_sync(0xffffffffu, i1, off);
            float ov2 = __shfl_xor_sync(0xffffffffu, v2, off);
            int   oi2 = __shfl_xor_sync(0xffffffffu, i2, off);
            top2_upd(v1, i1, v2, i2, ov1, oi1);
            top2_upd(v1, i1, v2, i2, ov2, oi2);
        }
        float p[4], zl = 0.0f;
#pragma unroll
        for (int q = 0; q < 4; q++) {
            p[q] = expf((v[q] - v1) * inv_temp);
            zl += p[q];
        }
#pragma unroll
        for (int off = 16; off > 0; off >>= 1)
            zl += __shfl_xor_sync(0xffffffffu, zl, off);
        float invZ = 1.0f / zl;
#pragma unroll
        for (int q = 0; q < 4; q++)
            atomicAdd(&sMe[ix[q]], p[q] * invZ);

        if (lane == 0) {
            int tok = tile * BM + t;
            out[tok * 2 + 0] = (float)i1;
            out[tok * 2 + 1] = (float)i2;
            float e  = expf(v2 - v1);
            float g1 = e / (1.0f + e);
            out[2 * T_TOKENS + tok * 2 + 0] = 1.0f - g1;
            out[2 * T_TOKENS + tok * 2 + 1] = g1;
            atomicAdd(&g_ce[i1], 1);
        }
    }
    __syncthreads();
    if (tid < N_EXP) atomicAdd(&g_me[tid], sMe[tid]);
}

__global__ void loss_kernel(float* __restrict__ out) {
    __shared__ float red[N_EXP];
    int i = threadIdx.x;
    red[i] = g_me[i] * (float)g_ce[i];
    __syncthreads();
    for (int s = 64; s > 0; s >>= 1) {
        if (i < s) red[i] += red[i + s];
        __syncthreads();
    }
    if (i == 0) {
        out[4 * T_TOKENS] = red[0] * ((float)N_EXP /
                              ((float)T_TOKENS * (float)T_TOKENS));
    }
}

extern "C" void kernel_launch(void* const* d_in, const int* in_sizes, int n_in,
                              void* d_out, int out_size) {
    const float* inp = (const float*)d_in[0];
    const float* wg  = (const float*)d_in[1];
    float* out = (float*)d_out;

    int nsm = 148;
    cudaDeviceGetAttribute(&nsm, cudaDevAttrMultiProcessorCount, 0);
    if (nsm < 1 || nsm > NUNITS) nsm = 148;

    prep_b_kernel<<<2048, 256>>>(wg);

    cudaFuncSetAttribute(gate_kernel,
                         cudaFuncAttributeMaxDynamicSharedMemorySize,
                         SMEM_TOTAL);
    gate_kernel<<<nsm, TPB, SMEM_TOTAL>>>(inp);

    epilogue_kernel<<<NTILE, 256>>>(out);
    loss_kernel<<<1, N_EXP>>>(out);
}